// round 14
// baseline (speedup 1.0000x reference)
#include <cuda_runtime.h>
#include <cuda_fp16.h>
#include <math.h>
#include <stdint.h>

#define Bb 32
#define Ll 512
#define Hh 768
#define Nn 64
#define NLl 4

// ---------------- device scratch ----------------
__device__ __align__(16) half  g_uh[(size_t)Bb * Hh * Ll];   // LN1 out fp16 [B,H,L]; conv overwrites in-place
__device__ __align__(16) half  g_z[(size_t)Bb * Ll * Hh];    // GEMM output fp16 [B,L,H]
__device__ __align__(16) float g_K[(size_t)NLl * 2 * Hh * Ll]; // conv kernels [NL,2,H,L]
__device__ float g_mu[Bb * Ll];
__device__ float g_rs[Bb * Ll];
__device__ __align__(16) half g_wh[(size_t)NLl * Hh * Hh];   // W fp16

__device__ __forceinline__ float gelu_tanh(float x) {
    float x3 = x * x * x;
    return 0.5f * x * (1.0f + tanhf(0.7978845608028654f * (x + 0.044715f * x3)));
}
__device__ __forceinline__ uint32_t smem_u32(const void* p) {
    uint32_t a;
    asm("{ .reg .u64 t; cvta.to.shared.u64 t, %1; cvt.u32.u64 %0, t; }" : "=r"(a) : "l"(p));
    return a;
}
__device__ __forceinline__ void cp16(uint32_t saddr, const void* g) {
    asm volatile("cp.async.ca.shared.global [%0], [%1], 16;" :: "r"(saddr), "l"(g) : "memory");
}
__device__ __forceinline__ void cp_commit() { asm volatile("cp.async.commit_group;" ::: "memory"); }
__device__ __forceinline__ void cp_wait1()  { asm volatile("cp.async.wait_group 1;" ::: "memory"); }
__device__ __forceinline__ void cp_wait0()  { asm volatile("cp.async.wait_group 0;" ::: "memory"); }
__device__ __forceinline__ void ldmx4(uint32_t* r, uint32_t addr) {
    asm volatile("ldmatrix.sync.aligned.m8n8.x4.shared.b16 {%0,%1,%2,%3}, [%4];"
        : "=r"(r[0]), "=r"(r[1]), "=r"(r[2]), "=r"(r[3]) : "r"(addr));
}
__device__ __forceinline__ void ldmx4t(uint32_t* r, uint32_t addr) {
    asm volatile("ldmatrix.sync.aligned.m8n8.x4.trans.shared.b16 {%0,%1,%2,%3}, [%4];"
        : "=r"(r[0]), "=r"(r[1]), "=r"(r[2]), "=r"(r[3]) : "r"(addr));
}
__device__ __forceinline__ void mma_f16(float* c, const uint32_t* a, uint32_t b0, uint32_t b1) {
    asm volatile("mma.sync.aligned.m16n8k16.row.col.f32.f16.f16.f32 "
        "{%0,%1,%2,%3}, {%4,%5,%6,%7}, {%8,%9}, {%0,%1,%2,%3};"
        : "+f"(c[0]), "+f"(c[1]), "+f"(c[2]), "+f"(c[3])
        : "r"(a[0]), "r"(a[1]), "r"(a[2]), "r"(a[3]), "r"(b0), "r"(b1));
}

// ---------------- fused x_in -> x copy + LN row statistics (layer 0 only) ----------------
__global__ void copystats_kernel(const float* __restrict__ xin, float* __restrict__ x) {
    int row = blockIdx.x;
    const float* xr = xin + (size_t)row * Hh;
    float* xo = x + (size_t)row * Hh;
    float v[3];
    float s = 0.f, ss = 0.f;
    #pragma unroll
    for (int q = 0; q < 3; q++) {
        int j = threadIdx.x + q * 256;
        v[q] = xr[j];
        xo[j] = v[q];
        s += v[q]; ss += v[q] * v[q];
    }
    for (int o = 16; o; o >>= 1) {
        s  += __shfl_down_sync(0xffffffffu, s, o);
        ss += __shfl_down_sync(0xffffffffu, ss, o);
    }
    __shared__ float s1[8], s2[8];
    int w = threadIdx.x >> 5;
    if ((threadIdx.x & 31) == 0) { s1[w] = s; s2[w] = ss; }
    __syncthreads();
    if (threadIdx.x == 0) {
        float S = 0.f, SS = 0.f;
        #pragma unroll
        for (int k = 0; k < 8; k++) { S += s1[k]; SS += s2[k]; }
        float mu = S / Hh;
        float var = SS / Hh - mu * mu;
        g_mu[row] = mu;
        g_rs[row] = rsqrtf(var + 1e-5f);
    }
}

// ---------------- LN1 apply + mask + transpose -> fp16 [B,H,L] (layer 0 only) ----------------
__global__ void ln1t_kernel(const float* __restrict__ x,
                            const float* __restrict__ w,
                            const float* __restrict__ bsh,
                            const int* __restrict__ mask) {
    __shared__ float tile[32][33];
    int b  = blockIdx.z;
    int l0 = blockIdx.x * 32, h0 = blockIdx.y * 32;
    int tx = threadIdx.x, ty = threadIdx.y;
    float wv = w[h0 + tx], bv = bsh[h0 + tx];
    #pragma unroll
    for (int k = 0; k < 4; k++) {
        int l   = l0 + ty + k * 8;
        int row = b * Ll + l;
        float v  = x[(size_t)row * Hh + h0 + tx];
        float mf = (float)mask[row];
        tile[ty + k * 8][tx] = ((v - g_mu[row]) * g_rs[row] * wv + bv) * mf;
    }
    __syncthreads();
    #pragma unroll
    for (int k = 0; k < 4; k++) {
        int h = h0 + ty + k * 8;
        g_uh[((size_t)b * Hh + h) * Ll + l0 + tx] = __float2half_rn(tile[tx][ty + k * 8]);
    }
}

// ---------------- S4D kernel K precompute, all layers (grid.y = layer) ----------------
__global__ void __launch_bounds__(64) kcomp_kernel(const float* __restrict__ log_dt,
                             const float* __restrict__ A_re,
                             const float* __restrict__ A_im,
                             const float* __restrict__ C_re,
                             const float* __restrict__ C_im) {
    int h = blockIdx.x;
    int layer = blockIdx.y;
    float* Kl = g_K + (size_t)layer * 2 * Hh * Ll;
    __shared__ float s_ar[Nn], s_ai[Nn];
    __shared__ float s_sr[Nn], s_si[Nn];
    __shared__ float s_c0r[Nn], s_c0i[Nn], s_c1r[Nn], s_c1i[Nn];
    int t = threadIdx.x;
    {
        float dt = expf(log_dt[layer * Hh + h]);
        float Ar = -expf(A_re[((size_t)layer * Hh + h) * Nn + t]);
        float Ai = A_im[((size_t)layer * Hh + h) * Nn + t];
        float ar = dt * Ar, ai = dt * Ai;
        float er = expf(ar), sn, cs;
        sincosf(ai, &sn, &cs);
        float zr = er * cs - 1.0f, zi = er * sn;
        float den = Ar * Ar + Ai * Ai;
        float wr = (zr * Ar + zi * Ai) / den;
        float wi = (zi * Ar - zr * Ai) / den;
        size_t c0 = ((size_t)(layer * 2 + 0) * Hh + h) * Nn + t;
        size_t c1 = ((size_t)(layer * 2 + 1) * Hh + h) * Nn + t;
        float cr0 = C_re[c0], ci0 = C_im[c0];
        float cr1 = C_re[c1], ci1 = C_im[c1];
        s_ar[t] = ar; s_ai[t] = ai;
        s_sr[t] = er * cs; s_si[t] = er * sn;
        s_c0r[t] = cr0 * wr - ci0 * wi;  s_c0i[t] = cr0 * wi + ci0 * wr;
        s_c1r[t] = cr1 * wr - ci1 * wi;  s_c1i[t] = cr1 * wi + ci1 * wr;
    }
    __syncthreads();

    int l0 = t * 8;
    float fl0 = (float)l0;
    float k0a[8], k1a[8];
    #pragma unroll
    for (int j = 0; j < 8; j++) { k0a[j] = 0.f; k1a[j] = 0.f; }

    for (int n = 0; n < Nn; n++) {
        float ar = s_ar[n], ai = s_ai[n];
        float e0 = expf(ar * fl0);
        float sn, cs;
        sincosf(ai * fl0, &sn, &cs);
        float vr = e0 * cs, vi = e0 * sn;
        float sr = s_sr[n], si = s_si[n];
        float c0r = s_c0r[n], c0i = s_c0i[n];
        float c1r = s_c1r[n], c1i = s_c1i[n];
        #pragma unroll
        for (int j = 0; j < 8; j++) {
            k0a[j] += c0r * vr - c0i * vi;
            k1a[j] += c1r * vr - c1i * vi;
            float nvr = vr * sr - vi * si;
            float nvi = vr * si + vi * sr;
            vr = nvr; vi = nvi;
        }
    }
    #pragma unroll
    for (int j = 0; j < 8; j++) {
        Kl[(size_t)h * Ll + l0 + j]        = 2.0f * k0a[j];
        Kl[((size_t)Hh + h) * Ll + l0 + j] = 2.0f * k1a[j];
    }
}

// ---------------- conv via block-Toeplitz mma.sync fp16: 32-batch CTA, dbuf M ----------------
#define USTRIDE 520          // halves per us row (512 + 8 pad)
#define MSTRIDE 72           // halves per M row
#define OFF_US 0             // 32 * 520 * 2 = 33280
#define OFF_CS 33280         // 1152 * 4     = 4608
#define OFF_M  37888         // 2 * 9216     = 18432
#define CONV_SMEM 56320

__device__ __forceinline__ void build_M(half* Mdst, const float* cs, int d, int t) {
    int p = t & 63, q0 = (t >> 6) * 16;
    int base = 576 + 64 * (d - 8) + q0 - p;
    half2 tmp[8];
    #pragma unroll
    for (int j = 0; j < 8; j++)
        tmp[j] = __floats2half2_rn(cs[base + 2 * j], cs[base + 2 * j + 1]);
    half2* dst = (half2*)(Mdst + p * MSTRIDE + q0);
    #pragma unroll
    for (int j = 0; j < 8; j++) dst[j] = tmp[j];
}

__global__ void __launch_bounds__(256) conv_tc_kernel(const float* __restrict__ Dvec,
                                                      const float* __restrict__ Kl) {
    extern __shared__ __align__(16) char sm[];
    half*  us = (half*)(sm + OFF_US);
    float* cs = (float*)(sm + OFF_CS);
    uint32_t us_a = smem_u32(us);
    uint32_t m_a  = smem_u32(sm + OFF_M);

    int t = threadIdx.x, lane = t & 31, wid = t >> 5;
    int h = blockIdx.x;

    // load u: 32 b-rows, 8 threads per row, 64 halves each
    {
        int row = t >> 3, c0 = (t & 7) * 64;
        const uint4* src = (const uint4*)(g_uh + ((size_t)row * Hh + h) * Ll + c0);
        uint4* dst = (uint4*)(us + row * USTRIDE + c0);
        #pragma unroll
        for (int j = 0; j < 8; j++) dst[j] = src[j];
    }
    // build c array: cs[576+dd]
    {
        const float* k0r = Kl + (size_t)h * Ll;
        const float* k1r = Kl + ((size_t)Hh + h) * Ll;
        float2 a = ((const float2*)k0r)[t];
        float2 b = ((const float2*)k1r)[t];
        cs[576 - 2 * t] = a.x;  cs[575 - 2 * t] = a.y;
        cs[577 + 2 * t] = b.x;  cs[578 + 2 * t] = b.y;
    }
    __syncthreads();

    float acc[4][4][4];
    #pragma unroll
    for (int i = 0; i < 4; i++)
        #pragma unroll
        for (int j = 0; j < 4; j++)
            #pragma unroll
            for (int q = 0; q < 4; q++) acc[i][j][q] = 0.f;

    build_M((half*)(sm + OFF_M + 9216), cs, 1, t);   // buf1 holds d=1
    __syncthreads();

    for (int d = 1; d <= 15; d++) {
        if (d < 15) build_M((half*)(sm + OFF_M + ((d & 1) ? 0 : 9216)), cs, d + 1, t);
        int jb = wid + d - 8;
        if (jb >= 0 && jb < 8) {
            uint32_t ma = m_a + ((d & 1) ? 9216u : 0u);
            #pragma unroll
            for (int ks = 0; ks < 4; ks++) {
                uint32_t ar[4][4];
                uint32_t abase = ma + (uint32_t)((lane & 15) * 144 + ks * 32 + (lane >> 4) * 16);
                #pragma unroll
                for (int mf = 0; mf < 4; mf++)
                    ldmx4(ar[mf], abase + (uint32_t)(mf * 2304));
                int nrow = (lane & 7) + ((lane >> 4) & 1) * 8;
                uint32_t bd = us_a + (uint32_t)(nrow * 1040 + jb * 128 + ks * 32 + ((lane >> 3) & 1) * 16);
                uint32_t br0[4], br1[4];
                ldmx4(br0, bd);
                ldmx4(br1, bd + 16 * 1040);
                #pragma unroll
                for (int mf = 0; mf < 4; mf++) {
                    mma_f16(acc[mf][0], ar[mf], br0[0], br0[1]);
                    mma_f16(acc[mf][1], ar[mf], br0[2], br0[3]);
                    mma_f16(acc[mf][2], ar[mf], br1[0], br1[1]);
                    mma_f16(acc[mf][3], ar[mf], br1[2], br1[3]);
                }
            }
        }
        __syncthreads();
    }

    // fused epilogue in place on us: y = gelu(conv + D*u)
    float dv = Dvec[h];
    #pragma unroll
    for (int mf = 0; mf < 4; mf++) {
        int l = wid * 64 + mf * 16 + (lane >> 2);
        #pragma unroll
        for (int nf = 0; nf < 4; nf++) {
            int b = nf * 8 + (lane & 3) * 2;
            float u0 = __half2float(us[b * USTRIDE + l]);
            float u1 = __half2float(us[(b + 1) * USTRIDE + l]);
            float u2 = __half2float(us[b * USTRIDE + l + 8]);
            float u3 = __half2float(us[(b + 1) * USTRIDE + l + 8]);
            us[b * USTRIDE + l]           = __float2half_rn(gelu_tanh(acc[mf][nf][0] + dv * u0));
            us[(b + 1) * USTRIDE + l]     = __float2half_rn(gelu_tanh(acc[mf][nf][1] + dv * u1));
            us[b * USTRIDE + l + 8]       = __float2half_rn(gelu_tanh(acc[mf][nf][2] + dv * u2));
            us[(b + 1) * USTRIDE + l + 8] = __float2half_rn(gelu_tanh(acc[mf][nf][3] + dv * u3));
        }
    }
    __syncthreads();

    // coalesced write back to g_uh [B,H,L]
    {
        int b = t >> 3, c = t & 7;
        half* orow = g_uh + ((size_t)b * Hh + h) * Ll;
        #pragma unroll
        for (int p = 0; p < 8; p++) {
            int lo_ = c * 8 + p * 64;
            *(uint4*)&orow[lo_] = *(const uint4*)&us[b * USTRIDE + lo_];
        }
    }
}

// ---------------- Wout fp32 -> fp16 (all layers once) ----------------
__global__ void cvtw_kernel(const float* __restrict__ Wout) {
    int i = blockIdx.x * 256 + threadIdx.x;
    g_wh[i] = __float2half_rn(Wout[i]);
}

// ---------------- mma.sync fp16 GEMM: 256 threads, 8 warps of 64x32, K32 2-stage ----------------
#define AST 272
#define A_BYTES (32 * 272)
#define B_BYTES (128 * 80)
#define GST3 (A_BYTES + B_BYTES)

__device__ __forceinline__ void gemm_issue3(uint32_t sbase, const half* ybase, int o0, int k0,
                                            const half* wl, int tid) {
    // A: 32 k-rows x 256B
    {
        int row = tid >> 4, c = tid & 15;
        #pragma unroll
        for (int p = 0; p < 2; p++) {
            int r = row + p * 16;
            cp16(sbase + (uint32_t)(r * AST + c * 16),
                 ybase + (size_t)(k0 + r) * Ll + c * 8);
        }
    }
    // B: 128 o-rows x 64B
    {
        int r = tid >> 2, c4 = tid & 3;
        #pragma unroll
        for (int p = 0; p < 2; p++) {
            int row = r + p * 64;
            cp16(sbase + A_BYTES + (uint32_t)(row * 80 + c4 * 16),
                 wl + (size_t)(o0 + row) * Hh + k0 + c4 * 8);
        }
    }
}

__global__ void __launch_bounds__(256) gemm_mma_kernel(const half* __restrict__ wl,
                                                       const float* __restrict__ bout) {
    extern __shared__ __align__(16) char sm[];
    uint32_t s0 = smem_u32(sm);
    int tid = threadIdx.x, lane = tid & 31, wid = tid >> 5;
    int wm = wid & 1, wn = wid >> 1;          // 2 m-halves x 4 n-quarters
    int m0 = blockIdx.y * 128, o0 = blockIdx.x * 128;
    int b  = m0 >> 9, l0 = m0 & 511;
    const half* ybase = g_uh + (size_t)b * Hh * Ll + l0;

    float acc[4][4][4];
    #pragma unroll
    for (int i = 0; i < 4; i++)
        #pragma unroll
        for (int j = 0; j < 4; j++)
            #pragma unroll
            for (int q = 0; q < 4; q++) acc[i][j][q] = 0.f;

    gemm_issue3(s0, ybase, o0, 0, wl, tid);
    cp_commit();

    const int NCH = Hh / 32;
    for (int c = 0; c < NCH; c++) {
        int st = c & 1;
        if (c + 1 < NCH) {
            gemm_issue3(s0 + (st ^ 1) * GST3, ybase, o0, (c + 1) * 32, wl, tid);
            cp_commit();
            cp_wait1();
        } else {
            cp_wait0();
        }
        __syncthreads();

        uint32_t sA = s0 + st * GST3;
        uint32_t sB = sA + A_BYTES;
        int g2 = (lane >> 4);
        int g1 = (lane >> 3) & 1;
        int ki = lane & 7;
        #pragma unroll
        for (int ks = 0; ks < 2; ks++) {
            uint32_t a[4][4];
            #pragma unroll
            for (int mf = 0; mf < 4; mf++) {
                uint32_t aaddr = sA
                    + (uint32_t)((ks * 16 + g2 * 8 + ki) * AST
                                 + (wm * 64 + mf * 16 + g1 * 8) * 2);
                ldmx4t(a[mf], aaddr);
            }
            #pragma unroll
            for (int ng = 0; ng < 2; ng++) {
                int nrow = wn * 32 + ng * 16 + (lane & 7) + ((lane >> 4) & 1) * 8;
                uint32_t bd = sB + (uint32_t)(nrow * 80 + ks * 32 + ((lane >> 3) & 1) * 16);
                uint32_t bh[4];
                ldmx4(bh, bd);
                #pragma unroll
                for (int mf = 0; mf < 4; mf++) {
                    mma_f16(acc[mf][ng * 2],     a[mf], bh[0], bh[1]);
                    mma_f16(acc[mf][ng * 2 + 1], a[mf], bh[2], bh[3]);
                }
            }
        }
        __syncthreads();
    }

    #pragma unroll
    for (int mf = 0; mf < 4; mf++) {
        int mrow = m0 + wm * 64 + mf * 16 + (lane >> 2);
        #pragma unroll
        for (int nf = 0; nf < 4; nf++) {
            int ncol = o0 + wn * 32 + nf * 8 + (lane & 3) * 2;
            float b0 = bout[ncol], b1 = bout[ncol + 1];
            half2* z0 = (half2*)(g_z + (size_t)mrow * Hh + ncol);
            half2* z1 = (half2*)(g_z + (size_t)(mrow + 8) * Hh + ncol);
            *z0 = __floats2half2_rn(acc[mf][nf][0] + b0, acc[mf][nf][1] + b1);
            *z1 = __floats2half2_rn(acc[mf][nf][2] + b0, acc[mf][nf][3] + b1);
        }
    }
}

// ---------------- fused LN2+residual + next-layer LN1 (16 L-rows/CTA, 48KB tile) ----------------
#define LNF_ROWS 16
#define LNF_SMEM (LNF_ROWS * 769 * 4)   // 49216

__global__ void __launch_bounds__(256) lnfuse_kernel(
        const float* __restrict__ w2, const float* __restrict__ b2,
        const float* __restrict__ w1, const float* __restrict__ b1,
        const int* __restrict__ mask, float* __restrict__ x, int do_ln1) {
    extern __shared__ __align__(16) float tile[];   // [16][769]
    __shared__ float smu1[LNF_ROWS], srs1[LNF_ROWS], smask[LNF_ROWS];
    int b = blockIdx.y, l0 = blockIdx.x * LNF_ROWS;
    int lane = threadIdx.x & 31, warp = threadIdx.x >> 5;

    #pragma unroll
    for (int q = 0; q < 2; q++) {
        int r = warp * 2 + q;
        size_t row = (size_t)(b * Ll + l0 + r);
        const half* zr = g_z + row * Hh;
        float* xr = x + row * Hh;
        float zv[24];
        float s = 0.f, ss = 0.f;
        #pragma unroll
        for (int j = 0; j < 24; j++) {
            zv[j] = __half2float(zr[lane + 32 * j]);
            s += zv[j]; ss += zv[j] * zv[j];
        }
        #pragma unroll
        for (int o = 16; o; o >>= 1) {
            s  += __shfl_xor_sync(0xffffffffu, s, o);
            ss += __shfl_xor_sync(0xffffffffu, ss, o);
        }
        float mu = s / Hh;
        float rs = rsqrtf(ss / Hh - mu * mu + 1e-5f);
        float s2 = 0.f, ss2 = 0.f;
        #pragma unroll
        for (int j = 0; j < 24; j++) {
            int col = lane + 32 * j;
            float xn = xr[col] + ((zv[j] - mu) * rs * w2[col] + b2[col]);
            xr[col] = xn;
            tile[r * 769 + col] = xn;
            s2 += xn; ss2 += xn * xn;
        }
        #pragma unroll
        for (int o = 16; o; o >>= 1) {
            s2  += __shfl_xor_sync(0xffffffffu, s2, o);
            ss2 += __shfl_xor_sync(0xffffffffu, ss2, o);
        }
        if (lane == 0) {
            float mu1 = s2 / Hh;
            smu1[r] = mu1;
            srs1[r] = rsqrtf(ss2 / Hh - mu1 * mu1 + 1e-5f);
            smask[r] = (float)mask[row];
        }
    }
    __syncthreads();
    if (!do_ln1) return;

    // phase 2: each thread owns 3 h values; writes 16 l (32B sector) per h
    #pragma unroll
    for (int hq = 0; hq < 3; hq++) {
        int h = threadIdx.x + hq * 256;
        float wv = w1[h], bv = b1[h];
        half hv[16];
        #pragma unroll
        for (int l = 0; l < LNF_ROWS; l++) {
            float xn = tile[l * 769 + h];
            float v = (xn - smu1[l]) * srs1[l] * wv + bv;
            hv[l] = __float2half_rn(v * smask[l]);
        }
        half* dst = g_uh + ((size_t)b * Hh + h) * Ll + l0;
        *(uint4*)&dst[0] = *(const uint4*)&hv[0];
        *(uint4*)&dst[8] = *(const uint4*)&hv[8];
    }
}

// ---------------- launch ----------------
extern "C" void kernel_launch(void* const* d_in, const int* in_sizes, int n_in,
                              void* d_out, int out_size) {
    const float* x_in   = (const float*)d_in[0];
    const int*   mask   = (const int*)  d_in[1];
    const float* ln1_w  = (const float*)d_in[2];
    const float* ln1_b  = (const float*)d_in[3];
    const float* log_dt = (const float*)d_in[4];
    const float* A_re   = (const float*)d_in[5];
    const float* A_im   = (const float*)d_in[6];
    const float* C_re   = (const float*)d_in[7];
    const float* C_im   = (const float*)d_in[8];
    const float* Dv     = (const float*)d_in[9];
    const float* Wout   = (const float*)d_in[10];
    const float* bout   = (const float*)d_in[11];
    const float* ln2_w  = (const float*)d_in[12];
    const float* ln2_b  = (const float*)d_in[13];
    float* x = (float*)d_out;

    cudaFuncSetAttribute(conv_tc_kernel, cudaFuncAttributeMaxDynamicSharedMemorySize, CONV_SMEM);
    cudaFuncSetAttribute(lnfuse_kernel, cudaFuncAttributeMaxDynamicSharedMemorySize, LNF_SMEM);

    cvtw_kernel<<<NLl * Hh * Hh / 256, 256>>>(Wout);
    kcomp_kernel<<<dim3(Hh, NLl), 64>>>(log_dt, A_re, A_im, C_re, C_im);
    copystats_kernel<<<Bb * Ll, 256>>>(x_in, x);
    ln1t_kernel<<<dim3(Ll / 32, Hh / 32, Bb), dim3(32, 8)>>>(x, ln1_w, ln1_b, mask);

    half* wh_base;
    float* k_base;
    cudaGetSymbolAddress((void**)&wh_base, g_wh);
    cudaGetSymbolAddress((void**)&k_base, g_K);

    for (int i = 0; i < NLl; i++) {
        conv_tc_kernel<<<Hh, 256, CONV_SMEM>>>(Dv + i * Hh, k_base + (size_t)i * 2 * Hh * Ll);
        gemm_mma_kernel<<<dim3(Hh / 128, Bb * Ll / 128), 256, 2 * GST3>>>(
            wh_base + (size_t)i * Hh * Hh, bout + i * Hh);
        int last = (i == NLl - 1);
        lnfuse_kernel<<<dim3(Ll / LNF_ROWS, Bb), 256, LNF_SMEM>>>(
            ln2_w + i * Hh, ln2_b + i * Hh,
            ln1_w + (last ? 0 : (i + 1)) * Hh, ln1_b + (last ? 0 : (i + 1)) * Hh,
            mask, x, last ? 0 : 1);
    }
}

// round 15
// speedup vs baseline: 1.1050x; 1.1050x over previous
#include <cuda_runtime.h>
#include <cuda_fp16.h>
#include <math.h>
#include <stdint.h>

#define Bb 32
#define Ll 512
#define Hh 768
#define Nn 64
#define NLl 4

// ---------------- device scratch ----------------
__device__ __align__(16) half  g_uh[(size_t)Bb * Hh * Ll];   // LN1 out fp16 [B,H,L]; conv overwrites in-place
__device__ __align__(16) half  g_z[(size_t)Bb * Ll * Hh];    // GEMM output fp16 [B,L,H]
__device__ __align__(16) float g_K[(size_t)NLl * 2 * Hh * Ll]; // conv kernels [NL,2,H,L]
__device__ float g_mu[Bb * Ll];
__device__ float g_rs[Bb * Ll];
__device__ __align__(16) half g_wh[(size_t)NLl * Hh * Hh];   // W fp16

__device__ __forceinline__ float gelu_tanh(float x) {
    float x3 = x * x * x;
    return 0.5f * x * (1.0f + tanhf(0.7978845608028654f * (x + 0.044715f * x3)));
}
__device__ __forceinline__ uint32_t smem_u32(const void* p) {
    uint32_t a;
    asm("{ .reg .u64 t; cvta.to.shared.u64 t, %1; cvt.u32.u64 %0, t; }" : "=r"(a) : "l"(p));
    return a;
}
__device__ __forceinline__ void cp16(uint32_t saddr, const void* g) {
    asm volatile("cp.async.ca.shared.global [%0], [%1], 16;" :: "r"(saddr), "l"(g) : "memory");
}
__device__ __forceinline__ void cp_commit() { asm volatile("cp.async.commit_group;" ::: "memory"); }
__device__ __forceinline__ void cp_wait1()  { asm volatile("cp.async.wait_group 1;" ::: "memory"); }
__device__ __forceinline__ void cp_wait0()  { asm volatile("cp.async.wait_group 0;" ::: "memory"); }
__device__ __forceinline__ void ldmx4(uint32_t* r, uint32_t addr) {
    asm volatile("ldmatrix.sync.aligned.m8n8.x4.shared.b16 {%0,%1,%2,%3}, [%4];"
        : "=r"(r[0]), "=r"(r[1]), "=r"(r[2]), "=r"(r[3]) : "r"(addr));
}
__device__ __forceinline__ void ldmx4t(uint32_t* r, uint32_t addr) {
    asm volatile("ldmatrix.sync.aligned.m8n8.x4.trans.shared.b16 {%0,%1,%2,%3}, [%4];"
        : "=r"(r[0]), "=r"(r[1]), "=r"(r[2]), "=r"(r[3]) : "r"(addr));
}
__device__ __forceinline__ void mma_f16(float* c, const uint32_t* a, uint32_t b0, uint32_t b1) {
    asm volatile("mma.sync.aligned.m16n8k16.row.col.f32.f16.f16.f32 "
        "{%0,%1,%2,%3}, {%4,%5,%6,%7}, {%8,%9}, {%0,%1,%2,%3};"
        : "+f"(c[0]), "+f"(c[1]), "+f"(c[2]), "+f"(c[3])
        : "r"(a[0]), "r"(a[1]), "r"(a[2]), "r"(a[3]), "r"(b0), "r"(b1));
}

// ---------------- fused x_in -> x copy + LN row statistics (layer 0 only) ----------------
__global__ void copystats_kernel(const float* __restrict__ xin, float* __restrict__ x) {
    int row = blockIdx.x;
    const float* xr = xin + (size_t)row * Hh;
    float* xo = x + (size_t)row * Hh;
    float v[3];
    float s = 0.f, ss = 0.f;
    #pragma unroll
    for (int q = 0; q < 3; q++) {
        int j = threadIdx.x + q * 256;
        v[q] = xr[j];
        xo[j] = v[q];
        s += v[q]; ss += v[q] * v[q];
    }
    for (int o = 16; o; o >>= 1) {
        s  += __shfl_down_sync(0xffffffffu, s, o);
        ss += __shfl_down_sync(0xffffffffu, ss, o);
    }
    __shared__ float s1[8], s2[8];
    int w = threadIdx.x >> 5;
    if ((threadIdx.x & 31) == 0) { s1[w] = s; s2[w] = ss; }
    __syncthreads();
    if (threadIdx.x == 0) {
        float S = 0.f, SS = 0.f;
        #pragma unroll
        for (int k = 0; k < 8; k++) { S += s1[k]; SS += s2[k]; }
        float mu = S / Hh;
        float var = SS / Hh - mu * mu;
        g_mu[row] = mu;
        g_rs[row] = rsqrtf(var + 1e-5f);
    }
}

// ---------------- LN1 apply + mask + transpose -> fp16 [B,H,L] (layer 0 only) ----------------
__global__ void ln1t_kernel(const float* __restrict__ x,
                            const float* __restrict__ w,
                            const float* __restrict__ bsh,
                            const int* __restrict__ mask) {
    __shared__ float tile[32][33];
    int b  = blockIdx.z;
    int l0 = blockIdx.x * 32, h0 = blockIdx.y * 32;
    int tx = threadIdx.x, ty = threadIdx.y;
    float wv = w[h0 + tx], bv = bsh[h0 + tx];
    #pragma unroll
    for (int k = 0; k < 4; k++) {
        int l   = l0 + ty + k * 8;
        int row = b * Ll + l;
        float v  = x[(size_t)row * Hh + h0 + tx];
        float mf = (float)mask[row];
        tile[ty + k * 8][tx] = ((v - g_mu[row]) * g_rs[row] * wv + bv) * mf;
    }
    __syncthreads();
    #pragma unroll
    for (int k = 0; k < 4; k++) {
        int h = h0 + ty + k * 8;
        g_uh[((size_t)b * Hh + h) * Ll + l0 + tx] = __float2half_rn(tile[tx][ty + k * 8]);
    }
}

// ---------------- S4D kernel K precompute, all layers (grid.y = layer) ----------------
__global__ void __launch_bounds__(64) kcomp_kernel(const float* __restrict__ log_dt,
                             const float* __restrict__ A_re,
                             const float* __restrict__ A_im,
                             const float* __restrict__ C_re,
                             const float* __restrict__ C_im) {
    int h = blockIdx.x;
    int layer = blockIdx.y;
    float* Kl = g_K + (size_t)layer * 2 * Hh * Ll;
    __shared__ float s_ar[Nn], s_ai[Nn];
    __shared__ float s_sr[Nn], s_si[Nn];
    __shared__ float s_c0r[Nn], s_c0i[Nn], s_c1r[Nn], s_c1i[Nn];
    int t = threadIdx.x;
    {
        float dt = expf(log_dt[layer * Hh + h]);
        float Ar = -expf(A_re[((size_t)layer * Hh + h) * Nn + t]);
        float Ai = A_im[((size_t)layer * Hh + h) * Nn + t];
        float ar = dt * Ar, ai = dt * Ai;
        float er = expf(ar), sn, cs;
        sincosf(ai, &sn, &cs);
        float zr = er * cs - 1.0f, zi = er * sn;
        float den = Ar * Ar + Ai * Ai;
        float wr = (zr * Ar + zi * Ai) / den;
        float wi = (zi * Ar - zr * Ai) / den;
        size_t c0 = ((size_t)(layer * 2 + 0) * Hh + h) * Nn + t;
        size_t c1 = ((size_t)(layer * 2 + 1) * Hh + h) * Nn + t;
        float cr0 = C_re[c0], ci0 = C_im[c0];
        float cr1 = C_re[c1], ci1 = C_im[c1];
        s_ar[t] = ar; s_ai[t] = ai;
        s_sr[t] = er * cs; s_si[t] = er * sn;
        s_c0r[t] = cr0 * wr - ci0 * wi;  s_c0i[t] = cr0 * wi + ci0 * wr;
        s_c1r[t] = cr1 * wr - ci1 * wi;  s_c1i[t] = cr1 * wi + ci1 * wr;
    }
    __syncthreads();

    int l0 = t * 8;
    float fl0 = (float)l0;
    float k0a[8], k1a[8];
    #pragma unroll
    for (int j = 0; j < 8; j++) { k0a[j] = 0.f; k1a[j] = 0.f; }

    for (int n = 0; n < Nn; n++) {
        float ar = s_ar[n], ai = s_ai[n];
        float e0 = expf(ar * fl0);
        float sn, cs;
        sincosf(ai * fl0, &sn, &cs);
        float vr = e0 * cs, vi = e0 * sn;
        float sr = s_sr[n], si = s_si[n];
        float c0r = s_c0r[n], c0i = s_c0i[n];
        float c1r = s_c1r[n], c1i = s_c1i[n];
        #pragma unroll
        for (int j = 0; j < 8; j++) {
            k0a[j] += c0r * vr - c0i * vi;
            k1a[j] += c1r * vr - c1i * vi;
            float nvr = vr * sr - vi * si;
            float nvi = vr * si + vi * sr;
            vr = nvr; vi = nvi;
        }
    }
    #pragma unroll
    for (int j = 0; j < 8; j++) {
        Kl[(size_t)h * Ll + l0 + j]        = 2.0f * k0a[j];
        Kl[((size_t)Hh + h) * Ll + l0 + j] = 2.0f * k1a[j];
    }
}

// ---------------- conv via block-Toeplitz mma.sync fp16: 32-batch CTA, dbuf M ----------------
#define USTRIDE 520          // halves per us row (512 + 8 pad)
#define MSTRIDE 72           // halves per M row
#define OFF_US 0             // 32 * 520 * 2 = 33280
#define OFF_CS 33280         // 1152 * 4     = 4608
#define OFF_M  37888         // 2 * 9216     = 18432
#define CONV_SMEM 56320

__device__ __forceinline__ void build_M(half* Mdst, const float* cs, int d, int t) {
    int p = t & 63, q0 = (t >> 6) * 16;
    int base = 576 + 64 * (d - 8) + q0 - p;
    half2 tmp[8];
    #pragma unroll
    for (int j = 0; j < 8; j++)
        tmp[j] = __floats2half2_rn(cs[base + 2 * j], cs[base + 2 * j + 1]);
    half2* dst = (half2*)(Mdst + p * MSTRIDE + q0);
    #pragma unroll
    for (int j = 0; j < 8; j++) dst[j] = tmp[j];
}

__global__ void __launch_bounds__(256) conv_tc_kernel(const float* __restrict__ Dvec,
                                                      const float* __restrict__ Kl) {
    extern __shared__ __align__(16) char sm[];
    half*  us = (half*)(sm + OFF_US);
    float* cs = (float*)(sm + OFF_CS);
    uint32_t us_a = smem_u32(us);
    uint32_t m_a  = smem_u32(sm + OFF_M);

    int t = threadIdx.x, lane = t & 31, wid = t >> 5;
    int h = blockIdx.x;

    // load u: 32 b-rows, 8 threads per row, 64 halves each
    {
        int row = t >> 3, c0 = (t & 7) * 64;
        const uint4* src = (const uint4*)(g_uh + ((size_t)row * Hh + h) * Ll + c0);
        uint4* dst = (uint4*)(us + row * USTRIDE + c0);
        #pragma unroll
        for (int j = 0; j < 8; j++) dst[j] = src[j];
    }
    // build c array: cs[576+dd]
    {
        const float* k0r = Kl + (size_t)h * Ll;
        const float* k1r = Kl + ((size_t)Hh + h) * Ll;
        float2 a = ((const float2*)k0r)[t];
        float2 b = ((const float2*)k1r)[t];
        cs[576 - 2 * t] = a.x;  cs[575 - 2 * t] = a.y;
        cs[577 + 2 * t] = b.x;  cs[578 + 2 * t] = b.y;
    }
    __syncthreads();

    float acc[4][4][4];
    #pragma unroll
    for (int i = 0; i < 4; i++)
        #pragma unroll
        for (int j = 0; j < 4; j++)
            #pragma unroll
            for (int q = 0; q < 4; q++) acc[i][j][q] = 0.f;

    build_M((half*)(sm + OFF_M + 9216), cs, 1, t);   // buf1 holds d=1
    __syncthreads();

    for (int d = 1; d <= 15; d++) {
        if (d < 15) build_M((half*)(sm + OFF_M + ((d & 1) ? 0 : 9216)), cs, d + 1, t);
        int jb = wid + d - 8;
        if (jb >= 0 && jb < 8) {
            uint32_t ma = m_a + ((d & 1) ? 9216u : 0u);
            #pragma unroll
            for (int ks = 0; ks < 4; ks++) {
                uint32_t ar[4][4];
                uint32_t abase = ma + (uint32_t)((lane & 15) * 144 + ks * 32 + (lane >> 4) * 16);
                #pragma unroll
                for (int mf = 0; mf < 4; mf++)
                    ldmx4(ar[mf], abase + (uint32_t)(mf * 2304));
                int nrow = (lane & 7) + ((lane >> 4) & 1) * 8;
                uint32_t bd = us_a + (uint32_t)(nrow * 1040 + jb * 128 + ks * 32 + ((lane >> 3) & 1) * 16);
                uint32_t br0[4], br1[4];
                ldmx4(br0, bd);
                ldmx4(br1, bd + 16 * 1040);
                #pragma unroll
                for (int mf = 0; mf < 4; mf++) {
                    mma_f16(acc[mf][0], ar[mf], br0[0], br0[1]);
                    mma_f16(acc[mf][1], ar[mf], br0[2], br0[3]);
                    mma_f16(acc[mf][2], ar[mf], br1[0], br1[1]);
                    mma_f16(acc[mf][3], ar[mf], br1[2], br1[3]);
                }
            }
        }
        __syncthreads();
    }

    // fused epilogue in place on us: y = gelu(conv + D*u)
    float dv = Dvec[h];
    #pragma unroll
    for (int mf = 0; mf < 4; mf++) {
        int l = wid * 64 + mf * 16 + (lane >> 2);
        #pragma unroll
        for (int nf = 0; nf < 4; nf++) {
            int b = nf * 8 + (lane & 3) * 2;
            float u0 = __half2float(us[b * USTRIDE + l]);
            float u1 = __half2float(us[(b + 1) * USTRIDE + l]);
            float u2 = __half2float(us[b * USTRIDE + l + 8]);
            float u3 = __half2float(us[(b + 1) * USTRIDE + l + 8]);
            us[b * USTRIDE + l]           = __float2half_rn(gelu_tanh(acc[mf][nf][0] + dv * u0));
            us[(b + 1) * USTRIDE + l]     = __float2half_rn(gelu_tanh(acc[mf][nf][1] + dv * u1));
            us[b * USTRIDE + l + 8]       = __float2half_rn(gelu_tanh(acc[mf][nf][2] + dv * u2));
            us[(b + 1) * USTRIDE + l + 8] = __float2half_rn(gelu_tanh(acc[mf][nf][3] + dv * u3));
        }
    }
    __syncthreads();

    // coalesced write back to g_uh [B,H,L]
    {
        int b = t >> 3, c = t & 7;
        half* orow = g_uh + ((size_t)b * Hh + h) * Ll;
        #pragma unroll
        for (int p = 0; p < 8; p++) {
            int lo_ = c * 8 + p * 64;
            *(uint4*)&orow[lo_] = *(const uint4*)&us[b * USTRIDE + lo_];
        }
    }
}

// ---------------- Wout fp32 -> fp16 (all layers once) ----------------
__global__ void cvtw_kernel(const float* __restrict__ Wout) {
    int i = blockIdx.x * 256 + threadIdx.x;
    g_wh[i] = __float2half_rn(Wout[i]);
}

// ---------------- mma.sync fp16 GEMM: 128 threads, 4 warps of 64x64, K32 2-stage (R13) ----------------
#define AST 272
#define A_BYTES (32 * 272)
#define B_BYTES (128 * 80)
#define GST3 (A_BYTES + B_BYTES)

__device__ __forceinline__ void gemm_issue3(uint32_t sbase, const half* ybase, int o0, int k0,
                                            const half* wl, int tid) {
    {
        int row = tid >> 4, c = tid & 15;
        #pragma unroll
        for (int p = 0; p < 4; p++) {
            int r = row + p * 8;
            cp16(sbase + (uint32_t)(r * AST + c * 16),
                 ybase + (size_t)(k0 + r) * Ll + c * 8);
        }
    }
    {
        int r = tid >> 2, c4 = tid & 3;
        #pragma unroll
        for (int p = 0; p < 4; p++) {
            int row = r + p * 32;
            cp16(sbase + A_BYTES + (uint32_t)(row * 80 + c4 * 16),
                 wl + (size_t)(o0 + row) * Hh + k0 + c4 * 8);
        }
    }
}

__global__ void __launch_bounds__(128) gemm_mma_kernel(const half* __restrict__ wl,
                                                       const float* __restrict__ bout) {
    extern __shared__ __align__(16) char sm[];
    uint32_t s0 = smem_u32(sm);
    int tid = threadIdx.x, lane = tid & 31, wid = tid >> 5;
    int wm = wid & 1, wn = wid >> 1;
    int m0 = blockIdx.y * 128, o0 = blockIdx.x * 128;
    int b  = m0 >> 9, l0 = m0 & 511;
    const half* ybase = g_uh + (size_t)b * Hh * Ll + l0;

    float acc[4][8][4];
    #pragma unroll
    for (int i = 0; i < 4; i++)
        #pragma unroll
        for (int j = 0; j < 8; j++)
            #pragma unroll
            for (int q = 0; q < 4; q++) acc[i][j][q] = 0.f;

    gemm_issue3(s0, ybase, o0, 0, wl, tid);
    cp_commit();

    const int NCH = Hh / 32;
    for (int c = 0; c < NCH; c++) {
        int st = c & 1;
        if (c + 1 < NCH) {
            gemm_issue3(s0 + (st ^ 1) * GST3, ybase, o0, (c + 1) * 32, wl, tid);
            cp_commit();
            cp_wait1();
        } else {
            cp_wait0();
        }
        __syncthreads();

        uint32_t sA = s0 + st * GST3;
        uint32_t sB = sA + A_BYTES;
        int g2 = (lane >> 4);
        int g1 = (lane >> 3) & 1;
        int ki = lane & 7;
        #pragma unroll
        for (int ks = 0; ks < 2; ks++) {
            uint32_t a[4][4];
            #pragma unroll
            for (int mf = 0; mf < 4; mf++) {
                uint32_t aaddr = sA
                    + (uint32_t)((ks * 16 + g2 * 8 + ki) * AST
                                 + (wm * 64 + mf * 16 + g1 * 8) * 2);
                ldmx4t(a[mf], aaddr);
            }
            #pragma unroll
            for (int ng = 0; ng < 4; ng++) {
                int nrow = wn * 64 + ng * 16 + (lane & 7) + ((lane >> 4) & 1) * 8;
                uint32_t bd = sB + (uint32_t)(nrow * 80 + ks * 32 + ((lane >> 3) & 1) * 16);
                uint32_t bh[4];
                ldmx4(bh, bd);
                #pragma unroll
                for (int mf = 0; mf < 4; mf++) {
                    mma_f16(acc[mf][ng * 2],     a[mf], bh[0], bh[1]);
                    mma_f16(acc[mf][ng * 2 + 1], a[mf], bh[2], bh[3]);
                }
            }
        }
        __syncthreads();
    }

    #pragma unroll
    for (int mf = 0; mf < 4; mf++) {
        int mrow = m0 + wm * 64 + mf * 16 + (lane >> 2);
        #pragma unroll
        for (int nf = 0; nf < 8; nf++) {
            int ncol = o0 + wn * 64 + nf * 8 + (lane & 3) * 2;
            float b0 = bout[ncol], b1 = bout[ncol + 1];
            half2* z0 = (half2*)(g_z + (size_t)mrow * Hh + ncol);
            half2* z1 = (half2*)(g_z + (size_t)(mrow + 8) * Hh + ncol);
            *z0 = __floats2half2_rn(acc[mf][nf][0] + b0, acc[mf][nf][1] + b1);
            *z1 = __floats2half2_rn(acc[mf][nf][2] + b0, acc[mf][nf][3] + b1);
        }
    }
}

// ---------------- fused LN2+residual + next-layer LN1 (16 L-rows/CTA, 48KB tile) ----------------
#define LNF_ROWS 16
#define LNF_SMEM (LNF_ROWS * 769 * 4)   // 49216

__global__ void __launch_bounds__(256) lnfuse_kernel(
        const float* __restrict__ w2, const float* __restrict__ b2,
        const float* __restrict__ w1, const float* __restrict__ b1,
        const int* __restrict__ mask, float* __restrict__ x, int do_ln1) {
    extern __shared__ __align__(16) float tile[];   // [16][769]
    __shared__ float smu1[LNF_ROWS], srs1[LNF_ROWS], smask[LNF_ROWS];
    int b = blockIdx.y, l0 = blockIdx.x * LNF_ROWS;
    int lane = threadIdx.x & 31, warp = threadIdx.x >> 5;

    #pragma unroll
    for (int q = 0; q < 2; q++) {
        int r = warp * 2 + q;
        size_t row = (size_t)(b * Ll + l0 + r);
        const half* zr = g_z + row * Hh;
        float* xr = x + row * Hh;
        float zv[24];
        float s = 0.f, ss = 0.f;
        #pragma unroll
        for (int j = 0; j < 24; j++) {
            zv[j] = __half2float(zr[lane + 32 * j]);
            s += zv[j]; ss += zv[j] * zv[j];
        }
        #pragma unroll
        for (int o = 16; o; o >>= 1) {
            s  += __shfl_xor_sync(0xffffffffu, s, o);
            ss += __shfl_xor_sync(0xffffffffu, ss, o);
        }
        float mu = s / Hh;
        float rs = rsqrtf(ss / Hh - mu * mu + 1e-5f);
        float s2 = 0.f, ss2 = 0.f;
        #pragma unroll
        for (int j = 0; j < 24; j++) {
            int col = lane + 32 * j;
            float xn = xr[col] + ((zv[j] - mu) * rs * w2[col] + b2[col]);
            xr[col] = xn;
            tile[r * 769 + col] = xn;
            s2 += xn; ss2 += xn * xn;
        }
        #pragma unroll
        for (int o = 16; o; o >>= 1) {
            s2  += __shfl_xor_sync(0xffffffffu, s2, o);
            ss2 += __shfl_xor_sync(0xffffffffu, ss2, o);
        }
        if (lane == 0) {
            float mu1 = s2 / Hh;
            smu1[r] = mu1;
            srs1[r] = rsqrtf(ss2 / Hh - mu1 * mu1 + 1e-5f);
            smask[r] = (float)mask[row];
        }
    }
    __syncthreads();
    if (!do_ln1) return;

    // phase 2: each thread owns 3 h values; writes 16 l (32B sector) per h
    #pragma unroll
    for (int hq = 0; hq < 3; hq++) {
        int h = threadIdx.x + hq * 256;
        float wv = w1[h], bv = b1[h];
        half hv[16];
        #pragma unroll
        for (int l = 0; l < LNF_ROWS; l++) {
            float xn = tile[l * 769 + h];
            float v = (xn - smu1[l]) * srs1[l] * wv + bv;
            hv[l] = __float2half_rn(v * smask[l]);
        }
        half* dst = g_uh + ((size_t)b * Hh + h) * Ll + l0;
        *(uint4*)&dst[0] = *(const uint4*)&hv[0];
        *(uint4*)&dst[8] = *(const uint4*)&hv[8];
    }
}

// ---------------- launch ----------------
extern "C" void kernel_launch(void* const* d_in, const int* in_sizes, int n_in,
                              void* d_out, int out_size) {
    const float* x_in   = (const float*)d_in[0];
    const int*   mask   = (const int*)  d_in[1];
    const float* ln1_w  = (const float*)d_in[2];
    const float* ln1_b  = (const float*)d_in[3];
    const float* log_dt = (const float*)d_in[4];
    const float* A_re   = (const float*)d_in[5];
    const float* A_im   = (const float*)d_in[6];
    const float* C_re   = (const float*)d_in[7];
    const float* C_im   = (const float*)d_in[8];
    const float* Dv     = (const float*)d_in[9];
    const float* Wout   = (const float*)d_in[10];
    const float* bout   = (const float*)d_in[11];
    const float* ln2_w  = (const float*)d_in[12];
    const float* ln2_b  = (const float*)d_in[13];
    float* x = (float*)d_out;

    cudaFuncSetAttribute(conv_tc_kernel, cudaFuncAttributeMaxDynamicSharedMemorySize, CONV_SMEM);
    cudaFuncSetAttribute(lnfuse_kernel, cudaFuncAttributeMaxDynamicSharedMemorySize, LNF_SMEM);

    cvtw_kernel<<<NLl * Hh * Hh / 256, 256>>>(Wout);
    kcomp_kernel<<<dim3(Hh, NLl), 64>>>(log_dt, A_re, A_im, C_re, C_im);
    copystats_kernel<<<Bb * Ll, 256>>>(x_in, x);
    ln1t_kernel<<<dim3(Ll / 32, Hh / 32, Bb), dim3(32, 8)>>>(x, ln1_w, ln1_b, mask);

    half* wh_base;
    float* k_base;
    cudaGetSymbolAddress((void**)&wh_base, g_wh);
    cudaGetSymbolAddress((void**)&k_base, g_K);

    for (int i = 0; i < NLl; i++) {
        conv_tc_kernel<<<Hh, 256, CONV_SMEM>>>(Dv + i * Hh, k_base + (size_t)i * 2 * Hh * Ll);
        gemm_mma_kernel<<<dim3(Hh / 128, Bb * Ll / 128), 128, 2 * GST3>>>(
            wh_base + (size_t)i * Hh * Hh, bout + i * Hh);
        int last = (i == NLl - 1);
        lnfuse_kernel<<<dim3(Ll / LNF_ROWS, Bb), 256, LNF_SMEM>>>(
            ln2_w + i * Hh, ln2_b + i * Hh,
            ln1_w + (last ? 0 : (i + 1)) * Hh, ln1_b + (last ? 0 : (i + 1)) * Hh,
            mask, x, last ? 0 : 1);
    }
}

// round 16
// speedup vs baseline: 1.1211x; 1.0145x over previous
#include <cuda_runtime.h>
#include <cuda_fp16.h>
#include <math.h>
#include <stdint.h>

#define Bb 32
#define Ll 512
#define Hh 768
#define Nn 64
#define NLl 4

// ---------------- device scratch ----------------
__device__ __align__(16) half  g_uh[(size_t)Bb * Hh * Ll];   // LN1 out fp16 [B,H,L]; conv overwrites in-place
__device__ __align__(16) half  g_z[(size_t)Bb * Ll * Hh];    // GEMM output fp16 [B,L,H]
__device__ __align__(16) float g_K[(size_t)NLl * 2 * Hh * Ll]; // conv kernels [NL,2,H,L]
__device__ __align__(16) half g_wh[(size_t)NLl * Hh * Hh];   // W fp16

__device__ __forceinline__ float gelu_tanh(float x) {
    float x3 = x * x * x;
    return 0.5f * x * (1.0f + tanhf(0.7978845608028654f * (x + 0.044715f * x3)));
}
__device__ __forceinline__ uint32_t smem_u32(const void* p) {
    uint32_t a;
    asm("{ .reg .u64 t; cvta.to.shared.u64 t, %1; cvt.u32.u64 %0, t; }" : "=r"(a) : "l"(p));
    return a;
}
__device__ __forceinline__ void cp16(uint32_t saddr, const void* g) {
    asm volatile("cp.async.ca.shared.global [%0], [%1], 16;" :: "r"(saddr), "l"(g) : "memory");
}
__device__ __forceinline__ void cp_commit() { asm volatile("cp.async.commit_group;" ::: "memory"); }
__device__ __forceinline__ void cp_wait1()  { asm volatile("cp.async.wait_group 1;" ::: "memory"); }
__device__ __forceinline__ void cp_wait0()  { asm volatile("cp.async.wait_group 0;" ::: "memory"); }
__device__ __forceinline__ void ldmx4(uint32_t* r, uint32_t addr) {
    asm volatile("ldmatrix.sync.aligned.m8n8.x4.shared.b16 {%0,%1,%2,%3}, [%4];"
        : "=r"(r[0]), "=r"(r[1]), "=r"(r[2]), "=r"(r[3]) : "r"(addr));
}
__device__ __forceinline__ void ldmx4t(uint32_t* r, uint32_t addr) {
    asm volatile("ldmatrix.sync.aligned.m8n8.x4.trans.shared.b16 {%0,%1,%2,%3}, [%4];"
        : "=r"(r[0]), "=r"(r[1]), "=r"(r[2]), "=r"(r[3]) : "r"(addr));
}
__device__ __forceinline__ void mma_f16(float* c, const uint32_t* a, uint32_t b0, uint32_t b1) {
    asm volatile("mma.sync.aligned.m16n8k16.row.col.f32.f16.f16.f32 "
        "{%0,%1,%2,%3}, {%4,%5,%6,%7}, {%8,%9}, {%0,%1,%2,%3};"
        : "+f"(c[0]), "+f"(c[1]), "+f"(c[2]), "+f"(c[3])
        : "r"(a[0]), "r"(a[1]), "r"(a[2]), "r"(a[3]), "r"(b0), "r"(b1));
}

// ---------------- fused layer-0 prologue: x copy + LN1 stats/apply + mask + transpose ----------------
#define LNF_ROWS 16
#define LNF_SMEM (LNF_ROWS * 769 * 4)   // 49216

__global__ void __launch_bounds__(256) ln0_kernel(
        const float* __restrict__ xin, float* __restrict__ x,
        const float* __restrict__ w1, const float* __restrict__ b1,
        const int* __restrict__ mask) {
    extern __shared__ __align__(16) float tile[];   // [16][769]
    __shared__ float smu1[LNF_ROWS], srs1[LNF_ROWS], smask[LNF_ROWS];
    int b = blockIdx.y, l0 = blockIdx.x * LNF_ROWS;
    int lane = threadIdx.x & 31, warp = threadIdx.x >> 5;

    #pragma unroll
    for (int q = 0; q < 2; q++) {
        int r = warp * 2 + q;
        size_t row = (size_t)(b * Ll + l0 + r);
        const float* xr = xin + row * Hh;
        float* xo = x + row * Hh;
        float s = 0.f, ss = 0.f;
        #pragma unroll
        for (int j = 0; j < 24; j++) {
            int col = lane + 32 * j;
            float v = xr[col];
            xo[col] = v;
            tile[r * 769 + col] = v;
            s += v; ss += v * v;
        }
        #pragma unroll
        for (int o = 16; o; o >>= 1) {
            s  += __shfl_xor_sync(0xffffffffu, s, o);
            ss += __shfl_xor_sync(0xffffffffu, ss, o);
        }
        if (lane == 0) {
            float mu = s / Hh;
            smu1[r] = mu;
            srs1[r] = rsqrtf(ss / Hh - mu * mu + 1e-5f);
            smask[r] = (float)mask[row];
        }
    }
    __syncthreads();

    #pragma unroll
    for (int hq = 0; hq < 3; hq++) {
        int h = threadIdx.x + hq * 256;
        float wv = w1[h], bv = b1[h];
        half hv[16];
        #pragma unroll
        for (int l = 0; l < LNF_ROWS; l++) {
            float xn = tile[l * 769 + h];
            float v = (xn - smu1[l]) * srs1[l] * wv + bv;
            hv[l] = __float2half_rn(v * smask[l]);
        }
        half* dst = g_uh + ((size_t)b * Hh + h) * Ll + l0;
        *(uint4*)&dst[0] = *(const uint4*)&hv[0];
        *(uint4*)&dst[8] = *(const uint4*)&hv[8];
    }
}

// ---------------- S4D kernel K precompute, all layers (grid.y = layer) ----------------
__global__ void __launch_bounds__(64) kcomp_kernel(const float* __restrict__ log_dt,
                             const float* __restrict__ A_re,
                             const float* __restrict__ A_im,
                             const float* __restrict__ C_re,
                             const float* __restrict__ C_im) {
    int h = blockIdx.x;
    int layer = blockIdx.y;
    float* Kl = g_K + (size_t)layer * 2 * Hh * Ll;
    __shared__ float s_ar[Nn], s_ai[Nn];
    __shared__ float s_sr[Nn], s_si[Nn];
    __shared__ float s_c0r[Nn], s_c0i[Nn], s_c1r[Nn], s_c1i[Nn];
    int t = threadIdx.x;
    {
        float dt = expf(log_dt[layer * Hh + h]);
        float Ar = -expf(A_re[((size_t)layer * Hh + h) * Nn + t]);
        float Ai = A_im[((size_t)layer * Hh + h) * Nn + t];
        float ar = dt * Ar, ai = dt * Ai;
        float er = expf(ar), sn, cs;
        sincosf(ai, &sn, &cs);
        float zr = er * cs - 1.0f, zi = er * sn;
        float den = Ar * Ar + Ai * Ai;
        float wr = (zr * Ar + zi * Ai) / den;
        float wi = (zi * Ar - zr * Ai) / den;
        size_t c0 = ((size_t)(layer * 2 + 0) * Hh + h) * Nn + t;
        size_t c1 = ((size_t)(layer * 2 + 1) * Hh + h) * Nn + t;
        float cr0 = C_re[c0], ci0 = C_im[c0];
        float cr1 = C_re[c1], ci1 = C_im[c1];
        s_ar[t] = ar; s_ai[t] = ai;
        s_sr[t] = er * cs; s_si[t] = er * sn;
        s_c0r[t] = cr0 * wr - ci0 * wi;  s_c0i[t] = cr0 * wi + ci0 * wr;
        s_c1r[t] = cr1 * wr - ci1 * wi;  s_c1i[t] = cr1 * wi + ci1 * wr;
    }
    __syncthreads();

    int l0 = t * 8;
    float fl0 = (float)l0;
    float k0a[8], k1a[8];
    #pragma unroll
    for (int j = 0; j < 8; j++) { k0a[j] = 0.f; k1a[j] = 0.f; }

    for (int n = 0; n < Nn; n++) {
        float ar = s_ar[n], ai = s_ai[n];
        float e0 = expf(ar * fl0);
        float sn, cs;
        sincosf(ai * fl0, &sn, &cs);
        float vr = e0 * cs, vi = e0 * sn;
        float sr = s_sr[n], si = s_si[n];
        float c0r = s_c0r[n], c0i = s_c0i[n];
        float c1r = s_c1r[n], c1i = s_c1i[n];
        #pragma unroll
        for (int j = 0; j < 8; j++) {
            k0a[j] += c0r * vr - c0i * vi;
            k1a[j] += c1r * vr - c1i * vi;
            float nvr = vr * sr - vi * si;
            float nvi = vr * si + vi * sr;
            vr = nvr; vi = nvi;
        }
    }
    #pragma unroll
    for (int j = 0; j < 8; j++) {
        Kl[(size_t)h * Ll + l0 + j]        = 2.0f * k0a[j];
        Kl[((size_t)Hh + h) * Ll + l0 + j] = 2.0f * k1a[j];
    }
}

// ---------------- conv via block-Toeplitz mma.sync fp16: 32-batch CTA, dbuf M ----------------
#define USTRIDE 520          // halves per us row (512 + 8 pad)
#define MSTRIDE 72           // halves per M row
#define OFF_US 0             // 32 * 520 * 2 = 33280
#define OFF_CS 33280         // 1152 * 4     = 4608
#define OFF_M  37888         // 2 * 9216     = 18432
#define CONV_SMEM 56320

__device__ __forceinline__ void build_M(half* Mdst, const float* cs, int d, int t) {
    int p = t & 63, q0 = (t >> 6) * 16;
    int base = 576 + 64 * (d - 8) + q0 - p;
    half2 tmp[8];
    #pragma unroll
    for (int j = 0; j < 8; j++)
        tmp[j] = __floats2half2_rn(cs[base + 2 * j], cs[base + 2 * j + 1]);
    half2* dst = (half2*)(Mdst + p * MSTRIDE + q0);
    #pragma unroll
    for (int j = 0; j < 8; j++) dst[j] = tmp[j];
}

__global__ void __launch_bounds__(256) conv_tc_kernel(const float* __restrict__ Dvec,
                                                      const float* __restrict__ Kl) {
    extern __shared__ __align__(16) char sm[];
    half*  us = (half*)(sm + OFF_US);
    float* cs = (float*)(sm + OFF_CS);
    uint32_t us_a = smem_u32(us);
    uint32_t m_a  = smem_u32(sm + OFF_M);

    int t = threadIdx.x, lane = t & 31, wid = t >> 5;
    int h = blockIdx.x;

    // load u: 32 b-rows, 8 threads per row, 64 halves each
    {
        int row = t >> 3, c0 = (t & 7) * 64;
        const uint4* src = (const uint4*)(g_uh + ((size_t)row * Hh + h) * Ll + c0);
        uint4* dst = (uint4*)(us + row * USTRIDE + c0);
        #pragma unroll
        for (int j = 0; j < 8; j++) dst[j] = src[j];
    }
    // build c array: cs[576+dd]
    {
        const float* k0r = Kl + (size_t)h * Ll;
        const float* k1r = Kl + ((size_t)Hh + h) * Ll;
        float2 a = ((const float2*)k0r)[t];
        float2 b = ((const float2*)k1r)[t];
        cs[576 - 2 * t] = a.x;  cs[575 - 2 * t] = a.y;
        cs[577 + 2 * t] = b.x;  cs[578 + 2 * t] = b.y;
    }
    __syncthreads();

    float acc[4][4][4];
    #pragma unroll
    for (int i = 0; i < 4; i++)
        #pragma unroll
        for (int j = 0; j < 4; j++)
            #pragma unroll
            for (int q = 0; q < 4; q++) acc[i][j][q] = 0.f;

    build_M((half*)(sm + OFF_M + 9216), cs, 1, t);   // buf1 holds d=1
    __syncthreads();

    for (int d = 1; d <= 15; d++) {
        if (d < 15) build_M((half*)(sm + OFF_M + ((d & 1) ? 0 : 9216)), cs, d + 1, t);
        int jb = wid + d - 8;
        if (jb >= 0 && jb < 8) {
            uint32_t ma = m_a + ((d & 1) ? 9216u : 0u);
            #pragma unroll
            for (int ks = 0; ks < 4; ks++) {
                uint32_t ar[4][4];
                uint32_t abase = ma + (uint32_t)((lane & 15) * 144 + ks * 32 + (lane >> 4) * 16);
                #pragma unroll
                for (int mf = 0; mf < 4; mf++)
                    ldmx4(ar[mf], abase + (uint32_t)(mf * 2304));
                int nrow = (lane & 7) + ((lane >> 4) & 1) * 8;
                uint32_t bd = us_a + (uint32_t)(nrow * 1040 + jb * 128 + ks * 32 + ((lane >> 3) & 1) * 16);
                uint32_t br0[4], br1[4];
                ldmx4(br0, bd);
                ldmx4(br1, bd + 16 * 1040);
                #pragma unroll
                for (int mf = 0; mf < 4; mf++) {
                    mma_f16(acc[mf][0], ar[mf], br0[0], br0[1]);
                    mma_f16(acc[mf][1], ar[mf], br0[2], br0[3]);
                    mma_f16(acc[mf][2], ar[mf], br1[0], br1[1]);
                    mma_f16(acc[mf][3], ar[mf], br1[2], br1[3]);
                }
            }
        }
        __syncthreads();
    }

    // fused epilogue in place on us: y = gelu(conv + D*u)
    float dv = Dvec[h];
    #pragma unroll
    for (int mf = 0; mf < 4; mf++) {
        int l = wid * 64 + mf * 16 + (lane >> 2);
        #pragma unroll
        for (int nf = 0; nf < 4; nf++) {
            int b = nf * 8 + (lane & 3) * 2;
            float u0 = __half2float(us[b * USTRIDE + l]);
            float u1 = __half2float(us[(b + 1) * USTRIDE + l]);
            float u2 = __half2float(us[b * USTRIDE + l + 8]);
            float u3 = __half2float(us[(b + 1) * USTRIDE + l + 8]);
            us[b * USTRIDE + l]           = __float2half_rn(gelu_tanh(acc[mf][nf][0] + dv * u0));
            us[(b + 1) * USTRIDE + l]     = __float2half_rn(gelu_tanh(acc[mf][nf][1] + dv * u1));
            us[b * USTRIDE + l + 8]       = __float2half_rn(gelu_tanh(acc[mf][nf][2] + dv * u2));
            us[(b + 1) * USTRIDE + l + 8] = __float2half_rn(gelu_tanh(acc[mf][nf][3] + dv * u3));
        }
    }
    __syncthreads();

    // coalesced write back to g_uh [B,H,L]
    {
        int b = t >> 3, c = t & 7;
        half* orow = g_uh + ((size_t)b * Hh + h) * Ll;
        #pragma unroll
        for (int p = 0; p < 8; p++) {
            int lo_ = c * 8 + p * 64;
            *(uint4*)&orow[lo_] = *(const uint4*)&us[b * USTRIDE + lo_];
        }
    }
}

// ---------------- Wout fp32 -> fp16 (all layers once) ----------------
__global__ void cvtw_kernel(const float* __restrict__ Wout) {
    int i = blockIdx.x * 256 + threadIdx.x;
    g_wh[i] = __float2half_rn(Wout[i]);
}

// ---------------- mma.sync fp16 GEMM: 128 threads, 4 warps of 64x64, K32 2-stage (R13) ----------------
#define AST 272
#define A_BYTES (32 * 272)
#define B_BYTES (128 * 80)
#define GST3 (A_BYTES + B_BYTES)

__device__ __forceinline__ void gemm_issue3(uint32_t sbase, const half* ybase, int o0, int k0,
                                            const half* wl, int tid) {
    {
        int row = tid >> 4, c = tid & 15;
        #pragma unroll
        for (int p = 0; p < 4; p++) {
            int r = row + p * 8;
            cp16(sbase + (uint32_t)(r * AST + c * 16),
                 ybase + (size_t)(k0 + r) * Ll + c * 8);
        }
    }
    {
        int r = tid >> 2, c4 = tid & 3;
        #pragma unroll
        for (int p = 0; p < 4; p++) {
            int row = r + p * 32;
            cp16(sbase + A_BYTES + (uint32_t)(row * 80 + c4 * 16),
                 wl + (size_t)(o0 + row) * Hh + k0 + c4 * 8);
        }
    }
}

__global__ void __launch_bounds__(128) gemm_mma_kernel(const half* __restrict__ wl,
                                                       const float* __restrict__ bout) {
    extern __shared__ __align__(16) char sm[];
    uint32_t s0 = smem_u32(sm);
    int tid = threadIdx.x, lane = tid & 31, wid = tid >> 5;
    int wm = wid & 1, wn = wid >> 1;
    int m0 = blockIdx.y * 128, o0 = blockIdx.x * 128;
    int b  = m0 >> 9, l0 = m0 & 511;
    const half* ybase = g_uh + (size_t)b * Hh * Ll + l0;

    float acc[4][8][4];
    #pragma unroll
    for (int i = 0; i < 4; i++)
        #pragma unroll
        for (int j = 0; j < 8; j++)
            #pragma unroll
            for (int q = 0; q < 4; q++) acc[i][j][q] = 0.f;

    gemm_issue3(s0, ybase, o0, 0, wl, tid);
    cp_commit();

    const int NCH = Hh / 32;
    for (int c = 0; c < NCH; c++) {
        int st = c & 1;
        if (c + 1 < NCH) {
            gemm_issue3(s0 + (st ^ 1) * GST3, ybase, o0, (c + 1) * 32, wl, tid);
            cp_commit();
            cp_wait1();
        } else {
            cp_wait0();
        }
        __syncthreads();

        uint32_t sA = s0 + st * GST3;
        uint32_t sB = sA + A_BYTES;
        int g2 = (lane >> 4);
        int g1 = (lane >> 3) & 1;
        int ki = lane & 7;
        #pragma unroll
        for (int ks = 0; ks < 2; ks++) {
            uint32_t a[4][4];
            #pragma unroll
            for (int mf = 0; mf < 4; mf++) {
                uint32_t aaddr = sA
                    + (uint32_t)((ks * 16 + g2 * 8 + ki) * AST
                                 + (wm * 64 + mf * 16 + g1 * 8) * 2);
                ldmx4t(a[mf], aaddr);
            }
            #pragma unroll
            for (int ng = 0; ng < 4; ng++) {
                int nrow = wn * 64 + ng * 16 + (lane & 7) + ((lane >> 4) & 1) * 8;
                uint32_t bd = sB + (uint32_t)(nrow * 80 + ks * 32 + ((lane >> 3) & 1) * 16);
                uint32_t bh[4];
                ldmx4(bh, bd);
                #pragma unroll
                for (int mf = 0; mf < 4; mf++) {
                    mma_f16(acc[mf][ng * 2],     a[mf], bh[0], bh[1]);
                    mma_f16(acc[mf][ng * 2 + 1], a[mf], bh[2], bh[3]);
                }
            }
        }
        __syncthreads();
    }

    #pragma unroll
    for (int mf = 0; mf < 4; mf++) {
        int mrow = m0 + wm * 64 + mf * 16 + (lane >> 2);
        #pragma unroll
        for (int nf = 0; nf < 8; nf++) {
            int ncol = o0 + wn * 64 + nf * 8 + (lane & 3) * 2;
            float b0 = bout[ncol], b1 = bout[ncol + 1];
            half2* z0 = (half2*)(g_z + (size_t)mrow * Hh + ncol);
            half2* z1 = (half2*)(g_z + (size_t)(mrow + 8) * Hh + ncol);
            *z0 = __floats2half2_rn(acc[mf][nf][0] + b0, acc[mf][nf][1] + b1);
            *z1 = __floats2half2_rn(acc[mf][nf][2] + b0, acc[mf][nf][3] + b1);
        }
    }
}

// ---------------- fused LN2+residual + next-layer LN1 (16 L-rows/CTA, 48KB tile) ----------------
__global__ void __launch_bounds__(256) lnfuse_kernel(
        const float* __restrict__ w2, const float* __restrict__ b2,
        const float* __restrict__ w1, const float* __restrict__ b1,
        const int* __restrict__ mask, float* __restrict__ x, int do_ln1) {
    extern __shared__ __align__(16) float tile[];   // [16][769]
    __shared__ float smu1[LNF_ROWS], srs1[LNF_ROWS], smask[LNF_ROWS];
    int b = blockIdx.y, l0 = blockIdx.x * LNF_ROWS;
    int lane = threadIdx.x & 31, warp = threadIdx.x >> 5;

    #pragma unroll
    for (int q = 0; q < 2; q++) {
        int r = warp * 2 + q;
        size_t row = (size_t)(b * Ll + l0 + r);
        const half* zr = g_z + row * Hh;
        float* xr = x + row * Hh;
        float zv[24];
        float s = 0.f, ss = 0.f;
        #pragma unroll
        for (int j = 0; j < 24; j++) {
            zv[j] = __half2float(zr[lane + 32 * j]);
            s += zv[j]; ss += zv[j] * zv[j];
        }
        #pragma unroll
        for (int o = 16; o; o >>= 1) {
            s  += __shfl_xor_sync(0xffffffffu, s, o);
            ss += __shfl_xor_sync(0xffffffffu, ss, o);
        }
        float mu = s / Hh;
        float rs = rsqrtf(ss / Hh - mu * mu + 1e-5f);
        float s2 = 0.f, ss2 = 0.f;
        #pragma unroll
        for (int j = 0; j < 24; j++) {
            int col = lane + 32 * j;
            float xn = xr[col] + ((zv[j] - mu) * rs * w2[col] + b2[col]);
            xr[col] = xn;
            tile[r * 769 + col] = xn;
            s2 += xn; ss2 += xn * xn;
        }
        #pragma unroll
        for (int o = 16; o; o >>= 1) {
            s2  += __shfl_xor_sync(0xffffffffu, s2, o);
            ss2 += __shfl_xor_sync(0xffffffffu, ss2, o);
        }
        if (lane == 0) {
            float mu1 = s2 / Hh;
            smu1[r] = mu1;
            srs1[r] = rsqrtf(ss2 / Hh - mu1 * mu1 + 1e-5f);
            smask[r] = (float)mask[row];
        }
    }
    __syncthreads();
    if (!do_ln1) return;

    // phase 2: each thread owns 3 h values; writes 16 l (32B sector) per h
    #pragma unroll
    for (int hq = 0; hq < 3; hq++) {
        int h = threadIdx.x + hq * 256;
        float wv = w1[h], bv = b1[h];
        half hv[16];
        #pragma unroll
        for (int l = 0; l < LNF_ROWS; l++) {
            float xn = tile[l * 769 + h];
            float v = (xn - smu1[l]) * srs1[l] * wv + bv;
            hv[l] = __float2half_rn(v * smask[l]);
        }
        half* dst = g_uh + ((size_t)b * Hh + h) * Ll + l0;
        *(uint4*)&dst[0] = *(const uint4*)&hv[0];
        *(uint4*)&dst[8] = *(const uint4*)&hv[8];
    }
}

// ---------------- launch ----------------
extern "C" void kernel_launch(void* const* d_in, const int* in_sizes, int n_in,
                              void* d_out, int out_size) {
    const float* x_in   = (const float*)d_in[0];
    const int*   mask   = (const int*)  d_in[1];
    const float* ln1_w  = (const float*)d_in[2];
    const float* ln1_b  = (const float*)d_in[3];
    const float* log_dt = (const float*)d_in[4];
    const float* A_re   = (const float*)d_in[5];
    const float* A_im   = (const float*)d_in[6];
    const float* C_re   = (const float*)d_in[7];
    const float* C_im   = (const float*)d_in[8];
    const float* Dv     = (const float*)d_in[9];
    const float* Wout   = (const float*)d_in[10];
    const float* bout   = (const float*)d_in[11];
    const float* ln2_w  = (const float*)d_in[12];
    const float* ln2_b  = (const float*)d_in[13];
    float* x = (float*)d_out;

    cudaFuncSetAttribute(conv_tc_kernel, cudaFuncAttributeMaxDynamicSharedMemorySize, CONV_SMEM);
    cudaFuncSetAttribute(lnfuse_kernel, cudaFuncAttributeMaxDynamicSharedMemorySize, LNF_SMEM);
    cudaFuncSetAttribute(ln0_kernel, cudaFuncAttributeMaxDynamicSharedMemorySize, LNF_SMEM);

    cvtw_kernel<<<NLl * Hh * Hh / 256, 256>>>(Wout);
    kcomp_kernel<<<dim3(Hh, NLl), 64>>>(log_dt, A_re, A_im, C_re, C_im);
    ln0_kernel<<<dim3(Ll / LNF_ROWS, Bb), 256, LNF_SMEM>>>(x_in, x, ln1_w, ln1_b, mask);

    half* wh_base;
    float* k_base;
    cudaGetSymbolAddress((void**)&wh_base, g_wh);
    cudaGetSymbolAddress((void**)&k_base, g_K);

    for (int i = 0; i < NLl; i++) {
        conv_tc_kernel<<<Hh, 256, CONV_SMEM>>>(Dv + i * Hh, k_base + (size_t)i * 2 * Hh * Ll);
        gemm_mma_kernel<<<dim3(Hh / 128, Bb * Ll / 128), 128, 2 * GST3>>>(
            wh_base + (size_t)i * Hh * Hh, bout + i * Hh);
        int last = (i == NLl - 1);
        lnfuse_kernel<<<dim3(Ll / LNF_ROWS, Bb), 256, LNF_SMEM>>>(
            ln2_w + i * Hh, ln2_b + i * Hh,
            ln1_w + (last ? 0 : (i + 1)) * Hh, ln1_b + (last ? 0 : (i + 1)) * Hh,
            mask, x, last ? 0 : 1);
    }
}